// round 6
// baseline (speedup 1.0000x reference)
#include <cuda_runtime.h>
#include <cstdint>
#include <cstddef>

// Problem dims (fixed per reference)
#define DIMM      1024
#define DIM_INNER 2048
#define BATCH     4
#define SEQ       4096
#define MROWS     (BATCH * SEQ)        // 16384
#define HG_COLS   (2 * DIM_INNER)      // 4096

// Scratch: hg = x @ W_hg  [16384, 4096], h (scan output) [16384, 2048]
__device__ float g_hg[(size_t)MROWS * HG_COLS];
__device__ float g_h [(size_t)MROWS * DIM_INNER];

// ---------------------------------------------------------------------------
// Classic tiled SGEMM: C[M,N] = A[M,K] * B[K,N], all row-major, dims divisible
// by tile sizes (16384 / 4096 / 2048 / 1024 all are).
// BM=BN=128, BK=16, 256 threads, 8x8 per-thread tile.
// ---------------------------------------------------------------------------
#define BM 128
#define BN 128
#define BK 16
#define TM 8
#define TN 8

__global__ void __launch_bounds__(256, 2)
sgemm_kernel(const float* __restrict__ A, const float* __restrict__ B,
             float* __restrict__ C, int M, int N, int K)
{
    __shared__ float As[BK][BM];
    __shared__ float Bs[BK][BN];

    const int tid = threadIdx.x;
    const int ty  = tid >> 4;          // 0..15
    const int tx  = tid & 15;          // 0..15
    const int row0 = blockIdx.y * BM;
    const int col0 = blockIdx.x * BN;

    // A tile load mapping: 128 rows x 16 cols = 512 float4; 2 per thread
    const int a_row = tid >> 2;        // 0..63
    const int a_col = (tid & 3) * 4;   // 0,4,8,12
    // B tile load mapping: 16 rows x 128 cols = 512 float4; 2 per thread
    const int b_row = tid >> 5;        // 0..7
    const int b_col = (tid & 31) * 4;  // 0..124

    const float* Ag = A + (size_t)row0 * K;
    const float* Bg = B + col0;

    float acc[TM][TN];
#pragma unroll
    for (int i = 0; i < TM; i++)
#pragma unroll
        for (int j = 0; j < TN; j++) acc[i][j] = 0.0f;

    for (int kt = 0; kt < K; kt += BK) {
        // Load A tile (transposed into smem)
        float4 a0 = *(const float4*)(Ag + (size_t)(a_row)      * K + kt + a_col);
        float4 a1 = *(const float4*)(Ag + (size_t)(a_row + 64) * K + kt + a_col);
        As[a_col + 0][a_row]      = a0.x;
        As[a_col + 1][a_row]      = a0.y;
        As[a_col + 2][a_row]      = a0.z;
        As[a_col + 3][a_row]      = a0.w;
        As[a_col + 0][a_row + 64] = a1.x;
        As[a_col + 1][a_row + 64] = a1.y;
        As[a_col + 2][a_row + 64] = a1.z;
        As[a_col + 3][a_row + 64] = a1.w;
        // Load B tile (direct)
        float4 b0 = *(const float4*)(Bg + (size_t)(kt + b_row)     * N + b_col);
        float4 b1 = *(const float4*)(Bg + (size_t)(kt + b_row + 8) * N + b_col);
        *(float4*)&Bs[b_row][b_col]     = b0;
        *(float4*)&Bs[b_row + 8][b_col] = b1;

        __syncthreads();

#pragma unroll
        for (int k = 0; k < BK; k++) {
            float a[TM], b[TN];
            float4 av0 = *(const float4*)&As[k][ty * TM];
            float4 av1 = *(const float4*)&As[k][ty * TM + 4];
            float4 bv0 = *(const float4*)&Bs[k][tx * TN];
            float4 bv1 = *(const float4*)&Bs[k][tx * TN + 4];
            a[0] = av0.x; a[1] = av0.y; a[2] = av0.z; a[3] = av0.w;
            a[4] = av1.x; a[5] = av1.y; a[6] = av1.z; a[7] = av1.w;
            b[0] = bv0.x; b[1] = bv0.y; b[2] = bv0.z; b[3] = bv0.w;
            b[4] = bv1.x; b[5] = bv1.y; b[6] = bv1.z; b[7] = bv1.w;
#pragma unroll
            for (int i = 0; i < TM; i++)
#pragma unroll
                for (int j = 0; j < TN; j++)
                    acc[i][j] = fmaf(a[i], b[j], acc[i][j]);
        }
        __syncthreads();
    }

    // Store C
#pragma unroll
    for (int i = 0; i < TM; i++) {
        float* Cp = C + (size_t)(row0 + ty * TM + i) * N + col0 + tx * TN;
        float4 v0 = make_float4(acc[i][0], acc[i][1], acc[i][2], acc[i][3]);
        float4 v1 = make_float4(acc[i][4], acc[i][5], acc[i][6], acc[i][7]);
        *(float4*)(Cp)     = v0;
        *(float4*)(Cp + 4) = v1;
    }
}

// ---------------------------------------------------------------------------
// minGRU scan in LINEAR space (mathematically identical to the log-space
// Heinsen scan for these inputs; all quantities positive & bounded):
//   z_t = sigmoid(gate_t)
//   h_t = (1 - z_t) * h_{t-1} + z_t * (relu(hidden_t) + 0.5)
//       = h_{t-1} + z_t * ((relu(hidden_t)+0.5) - h_{t-1})
// One thread per (batch, channel); coalesced loads across channels.
// ---------------------------------------------------------------------------
__global__ void __launch_bounds__(64)
scan_kernel(const float* __restrict__ hg, float* __restrict__ hout)
{
    const int ch = blockIdx.x * blockDim.x + threadIdx.x;  // 0..8191
    const int b  = ch >> 11;           // / DIM_INNER
    const int c  = ch & (DIM_INNER - 1);

    const float* hgp = hg   + (size_t)b * SEQ * HG_COLS;
    float*       hp  = hout + (size_t)b * SEQ * DIM_INNER;

    float h = 0.0f;
    for (int t = 0; t < SEQ; t += 4) {
        float hid[4], gat[4];
#pragma unroll
        for (int u = 0; u < 4; u++) {
            hid[u] = hgp[(size_t)(t + u) * HG_COLS + c];
            gat[u] = hgp[(size_t)(t + u) * HG_COLS + DIM_INNER + c];
        }
#pragma unroll
        for (int u = 0; u < 4; u++) {
            float e = __expf(-gat[u]);
            float z = __fdividef(1.0f, 1.0f + e);
            float uu = fmaxf(hid[u], 0.0f) + 0.5f;
            h = fmaf(z, uu - h, h);
            hp[(size_t)(t + u) * DIM_INNER + c] = h;
        }
    }
}

// ---------------------------------------------------------------------------
// kernel_launch
// Inputs (metadata order): x [4,4096,1024] f32, W_hg [1024,4096] f32,
//                          W_out [2048,1024] f32. Output: [4,4096,1024] f32.
// ---------------------------------------------------------------------------
extern "C" void kernel_launch(void* const* d_in, const int* in_sizes, int n_in,
                              void* d_out, int out_size)
{
    const float* x     = (const float*)d_in[0];
    const float* W_hg  = (const float*)d_in[1];
    const float* W_out = (const float*)d_in[2];
    float*       out   = (float*)d_out;

    void* p_hg = nullptr;
    void* p_h  = nullptr;
    cudaGetSymbolAddress(&p_hg, g_hg);
    cudaGetSymbolAddress(&p_h,  g_h);

    // GEMM1: hg = x @ W_hg   [16384,1024] x [1024,4096]
    {
        dim3 grid(HG_COLS / BN, MROWS / BM);
        sgemm_kernel<<<grid, 256>>>(x, W_hg, (float*)p_hg, MROWS, HG_COLS, DIMM);
    }
    // Scan: 8192 channels, one thread each, spread over many SMs
    {
        int nch = BATCH * DIM_INNER;   // 8192
        scan_kernel<<<nch / 64, 64>>>((const float*)p_hg, (float*)p_h);
    }
    // GEMM2: out = h @ W_out  [16384,2048] x [2048,1024]
    {
        dim3 grid(DIMM / BN, MROWS / BM);
        sgemm_kernel<<<grid, 256>>>((const float*)p_h, W_out, out, MROWS, DIMM, DIM_INNER);
    }
}

// round 13
// speedup vs baseline: 3.0561x; 3.0561x over previous
#include <cuda_runtime.h>
#include <cstdint>
#include <cstddef>

#define DIMM      1024
#define DIM_INNER 2048
#define BATCH     4
#define SEQ       4096
#define MROWS     (BATCH * SEQ)        // 16384
#define HG_COLS   (2 * DIM_INNER)      // 4096

__device__ float g_hg [(size_t)MROWS * HG_COLS];
__device__ float g_h  [(size_t)MROWS * DIM_INNER];
__device__ float g_x  [(size_t)MROWS * DIMM];
__device__ float g_bt1[(size_t)HG_COLS * DIMM];      // W_hg^T  [4096,1024] tf32
__device__ float g_bt2[(size_t)DIMM * DIM_INNER];    // W_out^T [1024,2048] tf32

// ---------------- helpers ----------------
__device__ __forceinline__ float tf32r(float v) {
    float r; asm("cvt.rna.tf32.f32 %0, %1;" : "=f"(r) : "f"(v)); return r;
}
__device__ __forceinline__ uint32_t smem_u32(const void* p) {
    uint32_t a;
    asm("{ .reg .u64 t; cvta.to.shared.u64 t, %1; cvt.u32.u64 %0, t; }" : "=r"(a) : "l"(p));
    return a;
}
__device__ __forceinline__ void cp16(uint32_t s, const void* g) {
    asm volatile("cp.async.cg.shared.global [%0], [%1], 16;" :: "r"(s), "l"(g));
}

// ---------------------------------------------------------------------------
// tf32 mma.sync GEMM: C[M,Ntot] = A[M,K] * Bt[Ntot,K]^T  (A, Bt row-major,
// values pre-rounded to tf32). BM=BN=128, BK=16, 3-stage cp.async pipeline.
// 256 threads = 8 warps in a 2x4 grid of 64x32 warp tiles.
// Smem tiles stored with row stride 20 words -> conflict-free fragment LDS.
// ---------------------------------------------------------------------------
#define BK 16
#define SA 20                       // words per smem tile row (16 data + 4 pad)
#define STG_WORDS (128 * SA)        // 2560 words per tile per stage
#define NSTAGE 3
#define GSMEM_BYTES (2 * NSTAGE * STG_WORDS * 4)   // 61440

__device__ __forceinline__ void mma_tf32(float* d, const float* a, const float* b) {
    asm volatile(
        "mma.sync.aligned.m16n8k8.row.col.f32.tf32.tf32.f32 "
        "{%0,%1,%2,%3}, {%4,%5,%6,%7}, {%8,%9}, {%0,%1,%2,%3};"
        : "+f"(d[0]), "+f"(d[1]), "+f"(d[2]), "+f"(d[3])
        : "r"(__float_as_uint(a[0])), "r"(__float_as_uint(a[1])),
          "r"(__float_as_uint(a[2])), "r"(__float_as_uint(a[3])),
          "r"(__float_as_uint(b[0])), "r"(__float_as_uint(b[1])));
}

__global__ void __launch_bounds__(256, 2)
gemm_mma(const float* __restrict__ A, const float* __restrict__ Bt,
         float* __restrict__ C, int Ntot, int K)
{
    extern __shared__ float sm[];                 // [A stages | B stages]
    float* Asm = sm;
    float* Bsm = sm + NSTAGE * STG_WORDS;
    const uint32_t sA = smem_u32(Asm);
    const uint32_t sB = smem_u32(Bsm);

    const int tid  = threadIdx.x;
    const int wid  = tid >> 5;
    const int lane = tid & 31;
    const int lr   = lane >> 2;      // 0..7
    const int lc   = lane & 3;       // 0..3
    const int m0   = (wid >> 2) * 64;   // warp row offset in tile
    const int n0   = (wid & 3) * 32;    // warp col offset in tile
    const int row0 = blockIdx.y * 128;
    const int col0 = blockIdx.x * 128;
    const int KT   = K / BK;

    float acc[4][4][4];
#pragma unroll
    for (int mt = 0; mt < 4; mt++)
#pragma unroll
        for (int nt = 0; nt < 4; nt++)
#pragma unroll
            for (int i = 0; i < 4; i++) acc[mt][nt][i] = 0.0f;

    const float* Ag = A  + (size_t)row0 * K;
    const float* Bg = Bt + (size_t)col0 * K;

    // Per stage: A tile = 128 rows x 16 floats = 512 float4; 2 per thread.
    auto load_stage = [&](int s, int kt) {
        const uint32_t ab = sA + (uint32_t)s * STG_WORDS * 4;
        const uint32_t bb = sB + (uint32_t)s * STG_WORDS * 4;
        const int koff = kt * BK;
#pragma unroll
        for (int i = 0; i < 2; i++) {
            int idx = i * 256 + tid;
            int r = idx >> 2, c4 = idx & 3;
            cp16(ab + (uint32_t)(r * SA + c4 * 4) * 4, Ag + (size_t)r * K + koff + c4 * 4);
        }
#pragma unroll
        for (int i = 0; i < 2; i++) {
            int idx = i * 256 + tid;
            int r = idx >> 2, c4 = idx & 3;
            cp16(bb + (uint32_t)(r * SA + c4 * 4) * 4, Bg + (size_t)r * K + koff + c4 * 4);
        }
        asm volatile("cp.async.commit_group;");
    };

    load_stage(0, 0);
    load_stage(1, 1);

    for (int kt = 0; kt < KT; kt++) {
        if (kt + 1 < KT) asm volatile("cp.async.wait_group %0;" :: "n"(1));
        else             asm volatile("cp.async.wait_group %0;" :: "n"(0));
        __syncthreads();

        const int s = kt % NSTAGE;
        const float* As = Asm + s * STG_WORDS;
        const float* Bs = Bsm + s * STG_WORDS;

#pragma unroll
        for (int ks = 0; ks < 2; ks++) {
            const int k0 = ks * 8;
            float a[4][4], b[4][2];
#pragma unroll
            for (int mt = 0; mt < 4; mt++) {
                int base = (m0 + mt * 16 + lr) * SA + k0 + lc;
                a[mt][0] = As[base];
                a[mt][1] = As[base + 8 * SA];
                a[mt][2] = As[base + 4];
                a[mt][3] = As[base + 8 * SA + 4];
            }
#pragma unroll
            for (int nt = 0; nt < 4; nt++) {
                int base = (n0 + nt * 8 + lr) * SA + k0 + lc;
                b[nt][0] = Bs[base];
                b[nt][1] = Bs[base + 4];
            }
#pragma unroll
            for (int mt = 0; mt < 4; mt++)
#pragma unroll
                for (int nt = 0; nt < 4; nt++)
                    mma_tf32(acc[mt][nt], a[mt], b[nt]);
        }

        if (kt + 2 < KT) load_stage((kt + 2) % NSTAGE, kt + 2);
    }

    // Epilogue: c0,c1 = (row, 2*lc), (row, 2*lc+1); c2,c3 = row+8. float2 stores.
#pragma unroll
    for (int mt = 0; mt < 4; mt++) {
#pragma unroll
        for (int nt = 0; nt < 4; nt++) {
            int r = row0 + m0 + mt * 16 + lr;
            int c = col0 + n0 + nt * 8 + 2 * lc;
            float2 v0 = make_float2(acc[mt][nt][0], acc[mt][nt][1]);
            float2 v1 = make_float2(acc[mt][nt][2], acc[mt][nt][3]);
            *(float2*)(C + (size_t)r * Ntot + c)       = v0;
            *(float2*)(C + (size_t)(r + 8) * Ntot + c) = v1;
        }
    }
}

// ---------------------------------------------------------------------------
// Prep: tf32-round x; transpose+round weights
// ---------------------------------------------------------------------------
__global__ void round_x_kernel(const float* __restrict__ in, float* __restrict__ out, int n4)
{
    int i = blockIdx.x * blockDim.x + threadIdx.x;
    for (; i < n4; i += gridDim.x * blockDim.x) {
        float4 v = ((const float4*)in)[i];
        v.x = tf32r(v.x); v.y = tf32r(v.y); v.z = tf32r(v.z); v.w = tf32r(v.w);
        ((float4*)out)[i] = v;
    }
}

__global__ void transpose_tf32(const float* __restrict__ in, float* __restrict__ out,
                               int R, int Cc)   // out[c][r] = tf32r(in[r][c])
{
    __shared__ float t[32][33];
    int r = blockIdx.y * 32 + threadIdx.y;
    int c = blockIdx.x * 32 + threadIdx.x;
    t[threadIdx.y][threadIdx.x] = in[(size_t)r * Cc + c];
    __syncthreads();
    int orow = blockIdx.x * 32 + threadIdx.y;
    int ocol = blockIdx.y * 32 + threadIdx.x;
    out[(size_t)orow * R + ocol] = tf32r(t[threadIdx.x][threadIdx.y]);
}

// ---------------------------------------------------------------------------
// Scan (linear-space minGRU recurrence), U=16 double-buffered for MLP.
//   z_t = sigmoid(gate_t); h_t = h_{t-1} + z_t*((relu(hid_t)+0.5) - h_{t-1})
// Stores tf32-rounded h (A operand of GEMM2).
// ---------------------------------------------------------------------------
#define USZ 16
__global__ void __launch_bounds__(64)
scan_kernel(const float* __restrict__ hg, float* __restrict__ hout)
{
    const int ch = blockIdx.x * 64 + threadIdx.x;   // 0..8191
    const int b  = ch >> 11;
    const int c  = ch & (DIM_INNER - 1);
    const float* hgp = hg   + (size_t)b * SEQ * HG_COLS + c;
    float*       hp  = hout + (size_t)b * SEQ * DIM_INNER + c;

    float hid[USZ], gat[USZ], nh[USZ], ng[USZ];
#pragma unroll
    for (int u = 0; u < USZ; u++) {
        hid[u] = hgp[(size_t)u * HG_COLS];
        gat[u] = hgp[(size_t)u * HG_COLS + DIM_INNER];
    }
    float h = 0.0f;
    for (int t = 0; t < SEQ; t += USZ) {
        const int tn = t + USZ;
        if (tn < SEQ) {
#pragma unroll
            for (int u = 0; u < USZ; u++) {
                nh[u] = hgp[(size_t)(tn + u) * HG_COLS];
                ng[u] = hgp[(size_t)(tn + u) * HG_COLS + DIM_INNER];
            }
        }
#pragma unroll
        for (int u = 0; u < USZ; u++) {
            float e = __expf(-gat[u]);
            float z = __fdividef(1.0f, 1.0f + e);
            float uu = fmaxf(hid[u], 0.0f) + 0.5f;
            h = fmaf(z, uu - h, h);
            hp[(size_t)(t + u) * DIM_INNER] = tf32r(h);
        }
#pragma unroll
        for (int u = 0; u < USZ; u++) { hid[u] = nh[u]; gat[u] = ng[u]; }
    }
}

// ---------------------------------------------------------------------------
extern "C" void kernel_launch(void* const* d_in, const int* in_sizes, int n_in,
                              void* d_out, int out_size)
{
    const float* x     = (const float*)d_in[0];
    const float* W_hg  = (const float*)d_in[1];
    const float* W_out = (const float*)d_in[2];
    float*       out   = (float*)d_out;

    void *p_hg, *p_h, *p_x, *p_b1, *p_b2;
    cudaGetSymbolAddress(&p_hg, g_hg);
    cudaGetSymbolAddress(&p_h,  g_h);
    cudaGetSymbolAddress(&p_x,  g_x);
    cudaGetSymbolAddress(&p_b1, g_bt1);
    cudaGetSymbolAddress(&p_b2, g_bt2);

    cudaFuncSetAttribute(gemm_mma, cudaFuncAttributeMaxDynamicSharedMemorySize, GSMEM_BYTES);

    // Prep: round x, transpose+round weights
    round_x_kernel<<<1184, 256>>>(x, (float*)p_x, (MROWS * DIMM) / 4);
    {
        dim3 g1(HG_COLS / 32, DIMM / 32);
        transpose_tf32<<<g1, dim3(32, 32)>>>(W_hg, (float*)p_b1, DIMM, HG_COLS);
        dim3 g2(DIMM / 32, DIM_INNER / 32);
        transpose_tf32<<<g2, dim3(32, 32)>>>(W_out, (float*)p_b2, DIM_INNER, DIMM);
    }
    // GEMM1: hg = x @ W_hg   (A=[16384,1024], Bt=[4096,1024])
    {
        dim3 grid(HG_COLS / 128, MROWS / 128);
        gemm_mma<<<grid, 256, GSMEM_BYTES>>>((const float*)p_x, (const float*)p_b1,
                                             (float*)p_hg, HG_COLS, DIMM);
    }
    // Scan
    scan_kernel<<<(BATCH * DIM_INNER) / 64, 64>>>((const float*)p_hg, (float*)p_h);
    // GEMM2: out = h @ W_out  (A=[16384,2048], Bt=[1024,2048])
    {
        dim3 grid(DIMM / 128, MROWS / 128);
        gemm_mma<<<grid, 256, GSMEM_BYTES>>>((const float*)p_h, (const float*)p_b2,
                                             out, DIMM, DIM_INNER);
    }
}

// round 17
// speedup vs baseline: 3.4804x; 1.1388x over previous
#include <cuda_runtime.h>
#include <cstdint>
#include <cstddef>

#define DIMM      1024
#define DIM_INNER 2048
#define BATCH     4
#define SEQ       4096
#define MROWS     (BATCH * SEQ)        // 16384
#define HG_COLS   (2 * DIM_INNER)      // 4096

__device__ float g_hg [(size_t)MROWS * HG_COLS];     // GEMM1 out (normal layout)
__device__ float g_h  [(size_t)MROWS * DIM_INNER];   // scan out (A-perm layout)
__device__ float g_x  [(size_t)MROWS * DIMM];        // x (A-perm layout, tf32)
__device__ float g_bt1[(size_t)HG_COLS * DIMM];      // W_hg^T (B-perm, tf32)
__device__ float g_bt2[(size_t)DIMM * DIM_INNER];    // W_out^T (B-perm, tf32)

// ---------------- helpers ----------------
__device__ __forceinline__ float tf32r(float v) {
    float r; asm("cvt.rna.tf32.f32 %0, %1;" : "=f"(r) : "f"(v)); return r;
}
__device__ __forceinline__ uint32_t smem_u32(const void* p) {
    uint32_t a;
    asm("{ .reg .u64 t; cvta.to.shared.u64 t, %1; cvt.u32.u64 %0, t; }" : "=r"(a) : "l"(p));
    return a;
}
__device__ __forceinline__ void cp16(uint32_t s, const void* g) {
    asm volatile("cp.async.cg.shared.global [%0], [%1], 16;" :: "r"(s), "l"(g));
}

// Fragment-ordered ("perm") layouts for m16n8k8 tf32 mma.sync:
// A[m][k]: block (m>>4, k>>3), 128 floats: lane=((m&7)<<2)+(k&3),
//          i = ((m>>3)&1) + 2*((k>>2)&1)            (a0..a3 order)
// B[n][k]: block (n>>3, k>>4), 128 floats: lane=((n&7)<<2)+(k&3),
//          i = (k>>2)&3                              (covers two k8 steps)
__device__ __forceinline__ size_t apos(int m, int k, int K) {
    return ((size_t)(m >> 4) * (K >> 3) + (k >> 3)) * 128
         + (((m & 7) << 2) + (k & 3)) * 4 + ((m >> 3) & 1) + (((k >> 2) & 1) << 1);
}
__device__ __forceinline__ size_t bpos(int n, int k, int K) {
    return ((size_t)(n >> 3) * (K >> 4) + (k >> 4)) * 128
         + (((n & 7) << 2) + (k & 3)) * 4 + ((k >> 2) & 3);
}

__device__ __forceinline__ void mma_tf32(float* d, float4 a, float b0, float b1) {
    asm volatile(
        "mma.sync.aligned.m16n8k8.row.col.f32.tf32.tf32.f32 "
        "{%0,%1,%2,%3}, {%4,%5,%6,%7}, {%8,%9}, {%0,%1,%2,%3};"
        : "+f"(d[0]), "+f"(d[1]), "+f"(d[2]), "+f"(d[3])
        : "r"(__float_as_uint(a.x)), "r"(__float_as_uint(a.y)),
          "r"(__float_as_uint(a.z)), "r"(__float_as_uint(a.w)),
          "r"(__float_as_uint(b0)),  "r"(__float_as_uint(b1)));
}

// ---------------------------------------------------------------------------
// tf32 mma.sync GEMM on perm-layout operands.
// C[M,Ntot] = A[M,K] * Bt[Ntot,K]^T, C row-major.
// BM=BN=128, BK=32, NSTAGE=3, 256 thr = 8 warps (2x4), warp tile 64x32.
// Stage smem: A 8mb x 4kb x 512B = 16KB; B 16nb x 2kp x 512B = 16KB.
// ---------------------------------------------------------------------------
#define NSTAGE 3
#define STG_F 4096                            // floats per operand per stage
#define GSMEM_BYTES (2 * NSTAGE * STG_F * 4)  // 98304

__global__ void __launch_bounds__(256, 2)
gemm_mma(const float* __restrict__ A, const float* __restrict__ Bt,
         float* __restrict__ C, int Ntot, int K)
{
    extern __shared__ float sm[];
    float* Asm = sm;
    float* Bsm = sm + NSTAGE * STG_F;
    const uint32_t sA = smem_u32(Asm);
    const uint32_t sB = smem_u32(Bsm);

    const int tid  = threadIdx.x;
    const int wid  = tid >> 5;
    const int lane = tid & 31;
    const int lr   = lane >> 2;
    const int lc   = lane & 3;
    const int mbW  = (wid >> 2) * 4;     // warp first m-block (of 16 rows)
    const int nbW  = (wid & 3) * 4;      // warp first n-block (of 8 cols)
    const int row0 = blockIdx.y * 128;
    const int col0 = blockIdx.x * 128;
    const int KT   = K >> 5;

    float acc[4][4][4];
#pragma unroll
    for (int mt = 0; mt < 4; mt++)
#pragma unroll
        for (int nt = 0; nt < 4; nt++)
#pragma unroll
            for (int i = 0; i < 4; i++) acc[mt][nt][i] = 0.0f;

    const float* Ag0 = A  + (size_t)(row0 >> 4) * (K >> 3) * 128;
    const float* Bg0 = Bt + (size_t)(col0 >> 3) * (K >> 4) * 128;

    auto load_stage = [&](int s, int kt) {
        const uint32_t ab = sA + (uint32_t)s * STG_F * 4;
        const uint32_t bb = sB + (uint32_t)s * STG_F * 4;
        const float* Ag = Ag0 + (size_t)kt * 4 * 128;   // + kb offset
        const float* Bg = Bg0 + (size_t)kt * 2 * 128;   // + kp offset
#pragma unroll
        for (int j = 0; j < 4; j++) {                   // A: 1024 cp16
            int idx = j * 256 + tid;
            int blk = idx >> 5, chunk = idx & 31;       // blk: mbL*4+kbL
            int mbL = blk >> 2, kbL = blk & 3;
            cp16(ab + (uint32_t)(blk * 128 + chunk * 4) * 4,
                 Ag + (size_t)mbL * (K >> 3) * 128 + kbL * 128 + chunk * 4);
        }
#pragma unroll
        for (int j = 0; j < 4; j++) {                   // B: 1024 cp16
            int idx = j * 256 + tid;
            int blk = idx >> 5, chunk = idx & 31;       // blk: nbL*2+kpL
            int nbL = blk >> 1, kpL = blk & 1;
            cp16(bb + (uint32_t)(blk * 128 + chunk * 4) * 4,
                 Bg + (size_t)nbL * (K >> 4) * 128 + kpL * 128 + chunk * 4);
        }
        asm volatile("cp.async.commit_group;");
    };

    load_stage(0, 0);
    load_stage(1, 1);

    for (int kt = 0; kt < KT; kt++) {
        if (kt + 1 < KT) asm volatile("cp.async.wait_group %0;" :: "n"(1));
        else             asm volatile("cp.async.wait_group %0;" :: "n"(0));
        __syncthreads();

        const int s = kt % NSTAGE;
        const float* As = Asm + s * STG_F;
        const float* Bs = Bsm + s * STG_F;

        float4 bfrag[4];
#pragma unroll
        for (int ks = 0; ks < 4; ks++) {
            const int kp = ks >> 1;
            if ((ks & 1) == 0) {
#pragma unroll
                for (int nt = 0; nt < 4; nt++)
                    bfrag[nt] = *(const float4*)(Bs + ((nbW + nt) * 2 + kp) * 128 + lane * 4);
            }
            float4 af[4];
#pragma unroll
            for (int mt = 0; mt < 4; mt++)
                af[mt] = *(const float4*)(As + ((mbW + mt) * 4 + ks) * 128 + lane * 4);
#pragma unroll
            for (int mt = 0; mt < 4; mt++)
#pragma unroll
                for (int nt = 0; nt < 4; nt++) {
                    float b0 = (ks & 1) ? bfrag[nt].z : bfrag[nt].x;
                    float b1 = (ks & 1) ? bfrag[nt].w : bfrag[nt].y;
                    mma_tf32(acc[mt][nt], af[mt], b0, b1);
                }
        }

        if (kt + 2 < KT) load_stage((kt + 2) % NSTAGE, kt + 2);
    }

    // Epilogue: C row-major float2 stores
#pragma unroll
    for (int mt = 0; mt < 4; mt++) {
#pragma unroll
        for (int nt = 0; nt < 4; nt++) {
            int r = row0 + mbW * 16 + mt * 16 + lr;
            int c = col0 + nbW * 8 + nt * 8 + 2 * lc;
            *(float2*)(C + (size_t)r * Ntot + c)       = make_float2(acc[mt][nt][0], acc[mt][nt][1]);
            *(float2*)(C + (size_t)(r + 8) * Ntot + c) = make_float2(acc[mt][nt][2], acc[mt][nt][3]);
        }
    }
}

// ---------------------------------------------------------------------------
// Prep: x -> A-perm tf32; W -> transpose -> B-perm tf32
// ---------------------------------------------------------------------------
__global__ void round_x_kernel(const float* __restrict__ in, float* __restrict__ out, int n4)
{
    int i = blockIdx.x * blockDim.x + threadIdx.x;
    for (; i < n4; i += gridDim.x * blockDim.x) {
        float4 v = ((const float4*)in)[i];
        int m = i >> 8;                    // K = 1024 -> 256 float4 per row
        int k = (i << 2) & 1023;
        size_t base = apos(m, k, DIMM);    // j=0 position; j adds 4 floats (lane+1)
        out[base]      = tf32r(v.x);
        out[base + 4]  = tf32r(v.y);
        out[base + 8]  = tf32r(v.z);
        out[base + 12] = tf32r(v.w);
    }
}

__global__ void transpose_tf32(const float* __restrict__ in, float* __restrict__ out,
                               int R, int Cc)   // in [R,Cc]; out B-perm [Cc,R], K=R
{
    __shared__ float t[32][33];
    int r = blockIdx.y * 32 + threadIdx.y;
    int c = blockIdx.x * 32 + threadIdx.x;
    t[threadIdx.y][threadIdx.x] = in[(size_t)r * Cc + c];
    __syncthreads();
    int n = blockIdx.x * 32 + threadIdx.y;   // out row (N dim)
    int k = blockIdx.y * 32 + threadIdx.x;   // out col (K dim)
    out[bpos(n, k, R)] = tf32r(t[threadIdx.x][threadIdx.y]);
}

// ---------------------------------------------------------------------------
// Scan: linear-space minGRU recurrence; writes h in A-perm layout (K=2048).
// Pairs (t, t+8) are adjacent floats in the perm layout -> float2 stores.
// ---------------------------------------------------------------------------
#define USZ 16
__global__ void __launch_bounds__(64)
scan_kernel(const float* __restrict__ hg, float* __restrict__ hout)
{
    const int ch = blockIdx.x * 64 + threadIdx.x;   // 0..8191
    const int b  = ch >> 11;
    const int c  = ch & (DIM_INNER - 1);
    const float* hgp = hg + (size_t)b * SEQ * HG_COLS + c;

    float hid[USZ], gat[USZ], nh[USZ], ng[USZ], hv[USZ];
#pragma unroll
    for (int u = 0; u < USZ; u++) {
        hid[u] = hgp[(size_t)u * HG_COLS];
        gat[u] = hgp[(size_t)u * HG_COLS + DIM_INNER];
    }
    float h = 0.0f;
    for (int t = 0; t < SEQ; t += USZ) {
        const int tn = t + USZ;
        if (tn < SEQ) {
#pragma unroll
            for (int u = 0; u < USZ; u++) {
                nh[u] = hgp[(size_t)(tn + u) * HG_COLS];
                ng[u] = hgp[(size_t)(tn + u) * HG_COLS + DIM_INNER];
            }
        }
#pragma unroll
        for (int u = 0; u < USZ; u++) {
            float e = __expf(-gat[u]);
            float z = __fdividef(1.0f, 1.0f + e);
            float uu = fmaxf(hid[u], 0.0f) + 0.5f;
            h = fmaf(z, uu - h, h);
            hv[u] = tf32r(h);
        }
        {   // perm-layout block base for rows m0..m0+15, col c
            const int m0 = b * SEQ + t;                 // m0 % 16 == 0
            float* blkp = hout + ((size_t)(m0 >> 4) * (DIM_INNER >> 3) + (c >> 3)) * 128
                        + (c & 3) * 4 + (((c >> 2) & 1) << 1);
#pragma unroll
            for (int u = 0; u < 8; u++)
                *(float2*)(blkp + u * 16) = make_float2(hv[u], hv[u + 8]);
        }
#pragma unroll
        for (int u = 0; u < USZ; u++) { hid[u] = nh[u]; gat[u] = ng[u]; }
    }
}

// ---------------------------------------------------------------------------
extern "C" void kernel_launch(void* const* d_in, const int* in_sizes, int n_in,
                              void* d_out, int out_size)
{
    const float* x     = (const float*)d_in[0];
    const float* W_hg  = (const float*)d_in[1];
    const float* W_out = (const float*)d_in[2];
    float*       out   = (float*)d_out;

    void *p_hg, *p_h, *p_x, *p_b1, *p_b2;
    cudaGetSymbolAddress(&p_hg, g_hg);
    cudaGetSymbolAddress(&p_h,  g_h);
    cudaGetSymbolAddress(&p_x,  g_x);
    cudaGetSymbolAddress(&p_b1, g_bt1);
    cudaGetSymbolAddress(&p_b2, g_bt2);

    cudaFuncSetAttribute(gemm_mma, cudaFuncAttributeMaxDynamicSharedMemorySize, GSMEM_BYTES);

    // Prep: x -> perm tf32; weights -> transposed perm tf32
    round_x_kernel<<<1184, 256>>>(x, (float*)p_x, (MROWS * DIMM) / 4);
    {
        dim3 g1(HG_COLS / 32, DIMM / 32);
        transpose_tf32<<<g1, dim3(32, 32)>>>(W_hg, (float*)p_b1, DIMM, HG_COLS);
        dim3 g2(DIMM / 32, DIM_INNER / 32);
        transpose_tf32<<<g2, dim3(32, 32)>>>(W_out, (float*)p_b2, DIM_INNER, DIMM);
    }
    // GEMM1: hg = x @ W_hg
    {
        dim3 grid(HG_COLS / 128, MROWS / 128);
        gemm_mma<<<grid, 256, GSMEM_BYTES>>>((const float*)p_x, (const float*)p_b1,
                                             (float*)p_hg, HG_COLS, DIMM);
    }
    // Scan
    scan_kernel<<<(BATCH * DIM_INNER) / 64, 64>>>((const float*)p_hg, (float*)p_h);
    // GEMM2: out = h @ W_out
    {
        dim3 grid(DIMM / 128, MROWS / 128);
        gemm_mma<<<grid, 256, GSMEM_BYTES>>>((const float*)p_h, (const float*)p_b2,
                                             out, DIMM, DIM_INNER);
    }
}